// round 3
// baseline (speedup 1.0000x reference)
#include <cuda_runtime.h>
#include <math.h>

#define MAXN 50000

__device__ float g_buf0[MAXN * 150];
__device__ float g_buf1[MAXN * 150];
__device__ float g_buf2[MAXN * 150];
__device__ float g_dinv[MAXN];
__device__ int   g_deg[MAXN];
__device__ unsigned g_pool[192];

__device__ __forceinline__ float* buf(int i) {
    return i == 0 ? g_buf0 : (i == 1 ? g_buf1 : g_buf2);
}

__device__ __forceinline__ unsigned enc_f(float f) {
    unsigned u = __float_as_uint(f);
    return (u & 0x80000000u) ? ~u : (u | 0x80000000u);
}
__device__ __forceinline__ float dec_f(unsigned e) {
    unsigned u = (e & 0x80000000u) ? (e & 0x7FFFFFFFu) : ~e;
    return __uint_as_float(u);
}
#define ENC_NEG_INF 0x007FFFFFu

__global__ void init_kernel(int N) {
    int i = blockIdx.x * blockDim.x + threadIdx.x;
    if (i < N) g_deg[i] = 0;
    if (i < 192) g_pool[i] = ENC_NEG_INF;
}

__global__ void deg_kernel(const int* __restrict__ dst, int E) {
    int e = blockIdx.x * blockDim.x + threadIdx.x;
    if (e < E) atomicAdd(&g_deg[dst[e]], 1);
}

__global__ void dinv_kernel(int N) {
    int i = blockIdx.x * blockDim.x + threadIdx.x;
    if (i < N) g_dinv[i] = rsqrtf((float)(g_deg[i] + 1));  // +1 = self loop
}

// o0 = o1 = in * dinv[row]; in is external (isel<0 -> xp) or a scratch buffer
__global__ void scale_dual_kernel(const float* __restrict__ xp, int isel,
                                  int o0sel, int o1sel, int total, int d) {
    const float* in = (isel < 0) ? xp : buf(isel);
    float* o0 = buf(o0sel);
    float* o1 = buf(o1sel);
    int idx = blockIdx.x * blockDim.x + threadIdx.x;
    int stride = gridDim.x * blockDim.x;
    for (; idx < total; idx += stride) {
        float v = in[idx] * g_dinv[idx / d];
        o0[idx] = v;
        o1[idx] = v;
    }
}

// One warp per edge: out[dst] += g[src]  (atomic scatter, coalesced rows)
__global__ void scatter_kernel(int gsel, int osel,
                               const int* __restrict__ src,
                               const int* __restrict__ dst, int E, int d) {
    const float* g = buf(gsel);
    float* out = buf(osel);
    int gid = blockIdx.x * blockDim.x + threadIdx.x;
    int w = gid >> 5, lane = gid & 31;
    if (w >= E) return;
    int s = src[w], t = dst[w];
    const float* gs = g + (long)s * d;
    float* ot = out + (long)t * d;
    for (int c = lane; c < d; c += 32) atomicAdd(ot + c, gs[c]);
}

// K-tiled register-blocked GEMM (static smem < 48KB)
// pre_scale: scale input row by dinv; post_mode 0: +bias,relu ; 1: *dinv, dual store
__global__ void gemm_kernel(int isel, const float* __restrict__ Wg,
                            const float* __restrict__ bvec, int osel, int o2sel,
                            int N, int din, int dout, int pre_scale, int post_mode) {
    __shared__ float sW[32 * 152 + 8];
    __shared__ float sX[32 * 33];
    const float* in = buf(isel);
    float* out = buf(osel);
    float* out2 = buf(o2sel);

    const int TM = 4, TN = 4, RT = 8;
    int tid = threadIdx.x;
    int row0 = blockIdx.x * 32;
    int CT = (dout + TN - 1) / TN;
    int ntile = RT * CT;

    float acc[2][TM][TN];
#pragma unroll
    for (int j = 0; j < 2; j++)
#pragma unroll
        for (int m = 0; m < TM; m++)
#pragma unroll
            for (int n = 0; n < TN; n++) acc[j][m][n] = 0.f;

    for (int k0 = 0; k0 < din; k0 += 32) {
        int KT = min(32, din - k0);
        for (int i = tid; i < KT * dout; i += 256) sW[i] = Wg[k0 * dout + i];
        for (int i = tid; i < KT * 32; i += 256) {
            int kk = i >> 5, r = i & 31;
            int row = row0 + r;
            float v = 0.f;
            if (row < N) {
                v = in[(long)row * din + k0 + kk];
                if (pre_scale) v *= g_dinv[row];
            }
            sX[kk * 33 + r] = v;
        }
        __syncthreads();

        for (int j = 0, t = tid; t < ntile; t += 256, j++) {
            int rt = t & (RT - 1), ct = t >> 3;
            int r0 = rt * TM, c0 = ct * TN;
            for (int kk = 0; kk < KT; kk++) {
                float a[TM], b[TN];
#pragma unroll
                for (int m = 0; m < TM; m++) a[m] = sX[kk * 33 + r0 + m];
#pragma unroll
                for (int n = 0; n < TN; n++) b[n] = sW[kk * dout + c0 + n];
#pragma unroll
                for (int m = 0; m < TM; m++)
#pragma unroll
                    for (int n = 0; n < TN; n++)
                        acc[j][m][n] = fmaf(a[m], b[n], acc[j][m][n]);
            }
        }
        __syncthreads();
    }

    for (int j = 0, t = tid; t < ntile; t += 256, j++) {
        int rt = t & (RT - 1), ct = t >> 3;
        int r0 = rt * TM, c0 = ct * TN;
#pragma unroll
        for (int m = 0; m < TM; m++) {
            int row = row0 + r0 + m;
            if (row >= N) continue;
#pragma unroll
            for (int n = 0; n < TN; n++) {
                int c = c0 + n;
                if (c >= dout) continue;
                float v = acc[j][m][n];
                long off = (long)row * dout + c;
                if (post_mode == 0) {
                    v += bvec[c];
                    v = fmaxf(v, 0.f);
                    out[off] = v;
                } else {
                    v *= g_dinv[row];
                    out[off] = v;
                    out2[off] = v;
                }
            }
        }
    }
}

// z = relu(dinv*h + b3) @ Wo + bo ; segment-max via smem-staged encoded atomicMax
__global__ void final_kernel(int hsel, const float* __restrict__ b3,
                             const float* __restrict__ Wo, const float* __restrict__ bo,
                             const int* __restrict__ batch, int N) {
    const float* h = buf(hsel);
    __shared__ unsigned sp[192];
    int tid = threadIdx.x;
    if (tid < 192) sp[tid] = ENC_NEG_INF;
    __syncthreads();
    int i = blockIdx.x * blockDim.x + tid;
    if (i < N) {
        float di = g_dinv[i];
        float z0 = bo[0], z1 = bo[1], z2 = bo[2];
        const float* hr = h + (long)i * 50;
#pragma unroll
        for (int c = 0; c < 50; c++) {
            float v = fmaxf(fmaf(di, hr[c], b3[c]), 0.f);
            z0 = fmaf(v, Wo[c * 3 + 0], z0);
            z1 = fmaf(v, Wo[c * 3 + 1], z1);
            z2 = fmaf(v, Wo[c * 3 + 2], z2);
        }
        int g = batch[i];
        atomicMax(&sp[g * 3 + 0], enc_f(z0));
        atomicMax(&sp[g * 3 + 1], enc_f(z1));
        atomicMax(&sp[g * 3 + 2], enc_f(z2));
    }
    __syncthreads();
    if (tid < 192 && sp[tid] != ENC_NEG_INF) atomicMax(&g_pool[tid], sp[tid]);
}

__global__ void softmax_kernel(float* __restrict__ out) {
    int g = threadIdx.x;
    if (g < 64) {
        float a = dec_f(g_pool[3 * g + 0]);
        float b = dec_f(g_pool[3 * g + 1]);
        float c = dec_f(g_pool[3 * g + 2]);
        float m = fmaxf(a, fmaxf(b, c));
        float ea = expf(a - m), eb = expf(b - m), ec = expf(c - m);
        float s = ea + eb + ec;
        out[3 * g + 0] = ea / s;
        out[3 * g + 1] = eb / s;
        out[3 * g + 2] = ec / s;
    }
}

extern "C" void kernel_launch(void* const* d_in, const int* in_sizes, int n_in,
                              void* d_out, int out_size) {
    const float* x = (const float*)d_in[0];
    const int* ei = (const int*)d_in[1];      // int64 in reference -> int32 in harness
    const int* batch = (const int*)d_in[2];   // ditto
    const float* W1 = (const float*)d_in[3];
    const float* b1 = (const float*)d_in[4];
    const float* W2 = (const float*)d_in[5];
    const float* b2 = (const float*)d_in[6];
    const float* W3 = (const float*)d_in[7];
    const float* b3 = (const float*)d_in[8];
    const float* Wo = (const float*)d_in[9];
    const float* bo = (const float*)d_in[10];
    float* out = (float*)d_out;

    int N = in_sizes[0] / 36;
    int E = in_sizes[1] / 2;
    const int* src = ei;
    const int* dst = ei + E;

    const int T = 256;
    init_kernel<<<(N + T - 1) / T, T>>>(N);
    deg_kernel<<<(E + T - 1) / T, T>>>(dst, E);
    dinv_kernel<<<(N + T - 1) / T, T>>>(N);

    int gemm_grid = (N + 31) / 32;
    int scat_grid = (E + 7) / 8;  // 8 warps/block, 1 warp/edge

    // Layer 1: aggregate in 36-dim, then GEMM 36->75 (+bias, relu)
    scale_dual_kernel<<<2048, T>>>(x, -1, 0, 1, N * 36, 36);
    scatter_kernel<<<scat_grid, T>>>(0, 1, src, dst, E, 36);
    gemm_kernel<<<gemm_grid, T>>>(1, W1, b1, 2, 2, N, 36, 75, 1, 0);

    // Layer 2: aggregate in 75-dim, then GEMM 75->150 (+bias, relu)
    scale_dual_kernel<<<2048, T>>>(nullptr, 2, 0, 1, N * 75, 75);
    scatter_kernel<<<scat_grid, T>>>(0, 1, src, dst, E, 75);
    gemm_kernel<<<gemm_grid, T>>>(1, W2, b2, 2, 2, N, 75, 150, 1, 0);

    // Layer 3: GEMM 150->50 first (epilogue *dinv, dual store), then aggregate in 50-dim
    gemm_kernel<<<gemm_grid, T>>>(2, W3, b3, 0, 1, N, 150, 50, 0, 1);
    scatter_kernel<<<scat_grid, T>>>(0, 1, src, dst, E, 50);

    // Fused: relu(dinv*h+b3) @ Wo + bo, segment-max pool
    final_kernel<<<(N + T - 1) / T, T>>>(1, b3, Wo, bo, batch, N);
    softmax_kernel<<<1, 64>>>(out);
}

// round 4
// speedup vs baseline: 1.1831x; 1.1831x over previous
#include <cuda_runtime.h>
#include <math.h>

#define MAXN 50000
#define MAXE 400000

__device__ float g_buf0[MAXN * 150];
__device__ float g_buf1[MAXN * 150];
__device__ float g_buf2[MAXN * 150];
__device__ float g_dinv[MAXN];
__device__ int   g_deg[MAXN];
__device__ int   g_cur[MAXN];
__device__ int   g_rowptr[MAXN + 1];
__device__ int   g_col[MAXE];
__device__ unsigned g_pool[192];

__device__ __forceinline__ float* buf(int i) {
    return i == 0 ? g_buf0 : (i == 1 ? g_buf1 : g_buf2);
}

__device__ __forceinline__ unsigned enc_f(float f) {
    unsigned u = __float_as_uint(f);
    return (u & 0x80000000u) ? ~u : (u | 0x80000000u);
}
__device__ __forceinline__ float dec_f(unsigned e) {
    unsigned u = (e & 0x80000000u) ? (e & 0x7FFFFFFFu) : ~e;
    return __uint_as_float(u);
}
#define ENC_NEG_INF 0x007FFFFFu

__global__ void init_kernel(int N) {
    int i = blockIdx.x * blockDim.x + threadIdx.x;
    if (i < N) { g_deg[i] = 0; g_cur[i] = 0; }
    if (i < 192) g_pool[i] = ENC_NEG_INF;
}

__global__ void deg_kernel(const int* __restrict__ dst, int E) {
    int e = blockIdx.x * blockDim.x + threadIdx.x;
    if (e < E) atomicAdd(&g_deg[dst[e]], 1);
}

__global__ void dinv_kernel(int N) {
    int i = blockIdx.x * blockDim.x + threadIdx.x;
    if (i < N) g_dinv[i] = rsqrtf((float)(g_deg[i] + 1));  // +1 = self loop
}

// Single-block exclusive scan of g_deg -> g_rowptr (warp-shuffle based)
__global__ void scan_kernel(int N) {
    __shared__ int wsum[32];
    __shared__ int carry_s;
    int tid = threadIdx.x, lane = tid & 31, wid = tid >> 5;
    if (tid == 0) carry_s = 0;
    __syncthreads();
    for (int base = 0; base < N; base += 1024) {
        int i = base + tid;
        int v = (i < N) ? g_deg[i] : 0;
        int x = v;
#pragma unroll
        for (int off = 1; off < 32; off <<= 1) {
            int t = __shfl_up_sync(~0u, x, off);
            if (lane >= off) x += t;
        }
        if (lane == 31) wsum[wid] = x;
        __syncthreads();
        if (wid == 0) {
            int y = wsum[lane];
#pragma unroll
            for (int off = 1; off < 32; off <<= 1) {
                int t = __shfl_up_sync(~0u, y, off);
                if (lane >= off) y += t;
            }
            wsum[lane] = y;
        }
        __syncthreads();
        int incl = x + (wid ? wsum[wid - 1] : 0);
        int carry = carry_s;
        if (i < N) g_rowptr[i] = carry + incl - v;
        __syncthreads();
        if (tid == 1023) carry_s = carry + incl;
        __syncthreads();
    }
    if (threadIdx.x == 0) g_rowptr[N] = carry_s;
}

__global__ void fill_kernel(const int* __restrict__ src, const int* __restrict__ dst, int E) {
    int e = blockIdx.x * blockDim.x + threadIdx.x;
    if (e < E) {
        int t = dst[e];
        int pos = atomicAdd(&g_cur[t], 1);
        g_col[g_rowptr[t] + pos] = src[e];
    }
}

// g0 = x * dinv[row]  (only needed once, for the raw input)
__global__ void scale_kernel(const float* __restrict__ xp, int osel, int total, int d) {
    float* o = buf(osel);
    int idx = blockIdx.x * blockDim.x + threadIdx.x;
    int stride = gridDim.x * blockDim.x;
    for (; idx < total; idx += stride)
        o[idx] = xp[idx] * g_dinv[idx / d];
}

// CSR gather: one warp per dst node. out[t] = g[t] + sum_{s in N(t)} g[s]
__global__ void gather_kernel(int gsel, int osel, int N, int d) {
    const float* g = buf(gsel);
    float* out = buf(osel);
    int w = (blockIdx.x * blockDim.x + threadIdx.x) >> 5;
    int lane = threadIdx.x & 31;
    if (w >= N) return;
    int beg = g_rowptr[w], end = g_rowptr[w + 1];
    const float* gt = g + (long)w * d;
    float a0 = 0.f, a1 = 0.f, a2 = 0.f;
    bool p0 = lane < d, p1 = lane + 32 < d, p2 = lane + 64 < d;
    if (p0) a0 = gt[lane];
    if (p1) a1 = gt[lane + 32];
    if (p2) a2 = gt[lane + 64];
    for (int e0 = beg; e0 < end; e0 += 32) {
        int c = (e0 + lane < end) ? g_col[e0 + lane] : 0;
        int n = min(32, end - e0);
        for (int j = 0; j < n; j++) {
            int s = __shfl_sync(~0u, c, j);
            const float* gs = g + (long)s * d;
            if (p0) a0 += gs[lane];
            if (p1) a1 += gs[lane + 32];
            if (p2) a2 += gs[lane + 64];
        }
    }
    float* ot = out + (long)w * d;
    if (p0) ot[lane] = a0;
    if (p1) ot[lane + 32] = a1;
    if (p2) ot[lane + 64] = a2;
}

// K-tiled register-blocked GEMM. smem strides chosen for aligned LDS.128:
//   sW row stride 152 (mult of 8), sX row stride 36 (mult of 4).
// pre_scale: input row *= dinv[row]
// post_mode 0: v=relu(v+b)            1: v*=dinv            2: v=relu(v+b)*dinv
__global__ void gemm_kernel(int isel, const float* __restrict__ Wg,
                            const float* __restrict__ bvec, int osel,
                            int N, int din, int dout, int pre_scale, int post_mode) {
    __shared__ float sW[32 * 152 + 8];
    __shared__ float sX[32 * 36 + 8];
    const float* in = buf(isel);
    float* out = buf(osel);

    const int TM = 4, TN = 4, RT = 8;
    int tid = threadIdx.x;
    int row0 = blockIdx.x * 32;
    int CT = (dout + TN - 1) / TN;
    int ntile = RT * CT;

    float acc[2][TM][TN];
#pragma unroll
    for (int j = 0; j < 2; j++)
#pragma unroll
        for (int m = 0; m < TM; m++)
#pragma unroll
            for (int n = 0; n < TN; n++) acc[j][m][n] = 0.f;

    for (int k0 = 0; k0 < din; k0 += 32) {
        int KT = min(32, din - k0);
        for (int i = tid; i < KT * dout; i += 256) {
            int kk = i / dout, c = i - kk * dout;
            sW[kk * 152 + c] = Wg[(k0 + kk) * dout + c];
        }
        for (int i = tid; i < KT * 32; i += 256) {
            int kk = i >> 5, r = i & 31;
            int row = row0 + r;
            float v = 0.f;
            if (row < N) {
                v = in[(long)row * din + k0 + kk];
                if (pre_scale) v *= g_dinv[row];
            }
            sX[kk * 36 + r] = v;
        }
        __syncthreads();

        for (int j = 0, t = tid; t < ntile; t += 256, j++) {
            int rt = t & (RT - 1), ct = t >> 3;
            int r0 = rt * TM, c0 = ct * TN;
            for (int kk = 0; kk < KT; kk++) {
                float4 av = *(const float4*)&sX[kk * 36 + r0];
                float b[TN];
#pragma unroll
                for (int n = 0; n < TN; n++) b[n] = sW[kk * 152 + c0 + n];
                float a[TM] = {av.x, av.y, av.z, av.w};
#pragma unroll
                for (int m = 0; m < TM; m++)
#pragma unroll
                    for (int n = 0; n < TN; n++)
                        acc[j][m][n] = fmaf(a[m], b[n], acc[j][m][n]);
            }
        }
        __syncthreads();
    }

    for (int j = 0, t = tid; t < ntile; t += 256, j++) {
        int rt = t & (RT - 1), ct = t >> 3;
        int r0 = rt * TM, c0 = ct * TN;
#pragma unroll
        for (int m = 0; m < TM; m++) {
            int row = row0 + r0 + m;
            if (row >= N) continue;
            float di = g_dinv[row];
#pragma unroll
            for (int n = 0; n < TN; n++) {
                int c = c0 + n;
                if (c >= dout) continue;
                float v = acc[j][m][n];
                if (post_mode == 0) {
                    v = fmaxf(v + bvec[c], 0.f);
                } else if (post_mode == 1) {
                    v *= di;
                } else {
                    v = fmaxf(v + bvec[c], 0.f) * di;
                }
                out[(long)row * dout + c] = v;
            }
        }
    }
}

// z = relu(dinv*h + b3) @ Wo + bo ; segment-max via smem-staged encoded atomicMax
__global__ void final_kernel(int hsel, const float* __restrict__ b3,
                             const float* __restrict__ Wo, const float* __restrict__ bo,
                             const int* __restrict__ batch, int N) {
    const float* h = buf(hsel);
    __shared__ unsigned sp[192];
    int tid = threadIdx.x;
    if (tid < 192) sp[tid] = ENC_NEG_INF;
    __syncthreads();
    int i = blockIdx.x * blockDim.x + tid;
    if (i < N) {
        float di = g_dinv[i];
        float z0 = bo[0], z1 = bo[1], z2 = bo[2];
        const float* hr = h + (long)i * 50;
#pragma unroll
        for (int c = 0; c < 50; c++) {
            float v = fmaxf(fmaf(di, hr[c], b3[c]), 0.f);
            z0 = fmaf(v, Wo[c * 3 + 0], z0);
            z1 = fmaf(v, Wo[c * 3 + 1], z1);
            z2 = fmaf(v, Wo[c * 3 + 2], z2);
        }
        int g = batch[i];
        atomicMax(&sp[g * 3 + 0], enc_f(z0));
        atomicMax(&sp[g * 3 + 1], enc_f(z1));
        atomicMax(&sp[g * 3 + 2], enc_f(z2));
    }
    __syncthreads();
    if (tid < 192 && sp[tid] != ENC_NEG_INF) atomicMax(&g_pool[tid], sp[tid]);
}

__global__ void softmax_kernel(float* __restrict__ out) {
    int g = threadIdx.x;
    if (g < 64) {
        float a = dec_f(g_pool[3 * g + 0]);
        float b = dec_f(g_pool[3 * g + 1]);
        float c = dec_f(g_pool[3 * g + 2]);
        float m = fmaxf(a, fmaxf(b, c));
        float ea = expf(a - m), eb = expf(b - m), ec = expf(c - m);
        float s = ea + eb + ec;
        out[3 * g + 0] = ea / s;
        out[3 * g + 1] = eb / s;
        out[3 * g + 2] = ec / s;
    }
}

extern "C" void kernel_launch(void* const* d_in, const int* in_sizes, int n_in,
                              void* d_out, int out_size) {
    const float* x = (const float*)d_in[0];
    const int* ei = (const int*)d_in[1];
    const int* batch = (const int*)d_in[2];
    const float* W1 = (const float*)d_in[3];
    const float* b1 = (const float*)d_in[4];
    const float* W2 = (const float*)d_in[5];
    const float* b2 = (const float*)d_in[6];
    const float* W3 = (const float*)d_in[7];
    const float* b3 = (const float*)d_in[8];
    const float* Wo = (const float*)d_in[9];
    const float* bo = (const float*)d_in[10];
    float* out = (float*)d_out;

    int N = in_sizes[0] / 36;
    int E = in_sizes[1] / 2;
    const int* src = ei;
    const int* dst = ei + E;

    const int T = 256;
    int gemm_grid = (N + 31) / 32;
    int gath_grid = (N * 32 + T - 1) / T;  // 1 warp per node

    // CSR build
    init_kernel<<<(N + T - 1) / T, T>>>(N);
    deg_kernel<<<(E + T - 1) / T, T>>>(dst, E);
    dinv_kernel<<<(N + T - 1) / T, T>>>(N);
    scan_kernel<<<1, 1024>>>(N);
    fill_kernel<<<(E + T - 1) / T, T>>>(src, dst, E);

    // Layer 1: g0 = x*dinv -> gather(36) -> GEMM 36->75 (pre dinv, relu+b, *dinv)
    scale_kernel<<<1024, T>>>(x, 0, N * 36, 36);
    gather_kernel<<<gath_grid, T>>>(0, 1, N, 36);
    gemm_kernel<<<gemm_grid, T>>>(1, W1, b1, 2, N, 36, 75, 1, 2);

    // Layer 2: gather(75) -> GEMM 75->150 (pre dinv, relu+b)
    gather_kernel<<<gath_grid, T>>>(2, 0, N, 75);
    gemm_kernel<<<gemm_grid, T>>>(0, W2, b2, 1, N, 75, 150, 1, 0);

    // Layer 3: GEMM 150->50 (*dinv) -> gather(50)
    gemm_kernel<<<gemm_grid, T>>>(1, W3, b3, 2, N, 150, 50, 0, 1);
    gather_kernel<<<gath_grid, T>>>(2, 0, N, 50);

    // Fused output layer + pool + softmax
    final_kernel<<<(N + T - 1) / T, T>>>(0, b3, Wo, bo, batch, N);
    softmax_kernel<<<1, 64>>>(out);
}

// round 5
// speedup vs baseline: 1.4102x; 1.1920x over previous
#include <cuda_runtime.h>
#include <math.h>

#define MAXN 50000
#define MAXE 400000
#define NBLK ((MAXN + 1023) / 1024)

__device__ float g_buf0[MAXN * 150];
__device__ float g_buf1[MAXN * 150];
__device__ float g_buf2[MAXN * 150];
__device__ float g_dinv[MAXN];
__device__ int   g_deg[MAXN];
__device__ int   g_cur[MAXN];
__device__ int   g_rowptr[MAXN + 1];
__device__ int   g_col[MAXE];
__device__ int   g_part[64];
__device__ unsigned g_pool[192];

__device__ __forceinline__ float* buf(int i) {
    return i == 0 ? g_buf0 : (i == 1 ? g_buf1 : g_buf2);
}

__device__ __forceinline__ unsigned enc_f(float f) {
    unsigned u = __float_as_uint(f);
    return (u & 0x80000000u) ? ~u : (u | 0x80000000u);
}
__device__ __forceinline__ float dec_f(unsigned e) {
    unsigned u = (e & 0x80000000u) ? (e & 0x7FFFFFFFu) : ~e;
    return __uint_as_float(u);
}
#define ENC_NEG_INF 0x007FFFFFu

__global__ void init_kernel(int N) {
    int i = blockIdx.x * blockDim.x + threadIdx.x;
    if (i < N) { g_deg[i] = 0; g_cur[i] = 0; }
    if (i < 192) g_pool[i] = ENC_NEG_INF;
}

__global__ void deg_kernel(const int* __restrict__ dst, int E) {
    int e = blockIdx.x * blockDim.x + threadIdx.x;
    if (e < E) atomicAdd(&g_deg[dst[e]], 1);
}

// Per-1024-block sum of deg -> g_part[b]; also computes dinv.
__global__ void block_sum_kernel(int N) {
    __shared__ int wsum[32];
    int b = blockIdx.x, tid = threadIdx.x;
    int i = b * 1024 + tid;
    int v = (i < N) ? g_deg[i] : 0;
    if (i < N) g_dinv[i] = rsqrtf((float)(v + 1));  // +1 = self loop
    int s = v;
#pragma unroll
    for (int off = 16; off; off >>= 1) s += __shfl_down_sync(~0u, s, off);
    if ((tid & 31) == 0) wsum[tid >> 5] = s;
    __syncthreads();
    if (tid < 32) {
        int y = wsum[tid];
#pragma unroll
        for (int off = 16; off; off >>= 1) y += __shfl_down_sync(~0u, y, off);
        if (tid == 0) g_part[b] = y;
    }
}

// Single warp: exclusive scan of g_part[0..nblk), total -> g_rowptr[N]
__global__ void scan_part_kernel(int nblk, int N) {
    int lane = threadIdx.x;
    int carry = 0;
    for (int base = 0; base < nblk; base += 32) {
        int i = base + lane;
        int v = (i < nblk) ? g_part[i] : 0;
        int x = v;
#pragma unroll
        for (int off = 1; off < 32; off <<= 1) {
            int t = __shfl_up_sync(~0u, x, off);
            if (lane >= off) x += t;
        }
        if (i < nblk) g_part[i] = carry + x - v;
        carry += __shfl_sync(~0u, x, 31);
    }
    if (lane == 0) g_rowptr[N] = carry;
}

// Per-block exclusive scan of deg + block offset -> rowptr
__global__ void rowptr_kernel(int N) {
    __shared__ int wsum[32];
    int b = blockIdx.x, tid = threadIdx.x, lane = tid & 31, wid = tid >> 5;
    int i = b * 1024 + tid;
    int v = (i < N) ? g_deg[i] : 0;
    int x = v;
#pragma unroll
    for (int off = 1; off < 32; off <<= 1) {
        int t = __shfl_up_sync(~0u, x, off);
        if (lane >= off) x += t;
    }
    if (lane == 31) wsum[wid] = x;
    __syncthreads();
    if (wid == 0) {
        int y = wsum[lane];
#pragma unroll
        for (int off = 1; off < 32; off <<= 1) {
            int t = __shfl_up_sync(~0u, y, off);
            if (lane >= off) y += t;
        }
        wsum[lane] = y;
    }
    __syncthreads();
    int incl = x + (wid ? wsum[wid - 1] : 0);
    if (i < N) g_rowptr[i] = g_part[b] + incl - v;
}

__global__ void fill_kernel(const int* __restrict__ src, const int* __restrict__ dst, int E) {
    int e = blockIdx.x * blockDim.x + threadIdx.x;
    if (e < E) {
        int t = dst[e];
        int pos = atomicAdd(&g_cur[t], 1);
        g_col[g_rowptr[t] + pos] = src[e];
    }
}

// Fully-normalized CSR gather: out[t] = dinv[t] * sum_{s in N(t)+{t}} dinv[s]*g[s]
// One warp per dst node; input external (gsel<0 -> xp) or scratch buffer.
__global__ void gather_kernel(const float* __restrict__ xp, int gsel, int osel,
                              int N, int d) {
    const float* g = (gsel < 0) ? xp : buf(gsel);
    float* out = buf(osel);
    int w = (blockIdx.x * blockDim.x + threadIdx.x) >> 5;
    int lane = threadIdx.x & 31;
    if (w >= N) return;
    int beg = g_rowptr[w], end = g_rowptr[w + 1];
    float dt = g_dinv[w];
    const float* gt = g + (long)w * d;
    bool p0 = lane < d, p1 = lane + 32 < d, p2 = lane + 64 < d;
    float a0 = 0.f, a1 = 0.f, a2 = 0.f;
    if (p0) a0 = dt * gt[lane];
    if (p1) a1 = dt * gt[lane + 32];
    if (p2) a2 = dt * gt[lane + 64];
    for (int e0 = beg; e0 < end; e0 += 32) {
        bool act = e0 + lane < end;
        int c = act ? g_col[e0 + lane] : 0;
        float ds = act ? g_dinv[c] : 0.f;
        int n = min(32, end - e0);
        for (int j = 0; j < n; j++) {
            int s = __shfl_sync(~0u, c, j);
            float dsv = __shfl_sync(~0u, ds, j);
            const float* gs = g + (long)s * d;
            if (p0) a0 = fmaf(dsv, gs[lane], a0);
            if (p1) a1 = fmaf(dsv, gs[lane + 32], a1);
            if (p2) a2 = fmaf(dsv, gs[lane + 64], a2);
        }
    }
    float* ot = out + (long)w * d;
    if (p0) ot[lane] = dt * a0;
    if (p1) ot[lane + 32] = dt * a1;
    if (p2) ot[lane + 64] = dt * a2;
}

// K-tiled register-blocked GEMM. post_mode 0: relu(v+bias); 1: plain store
__global__ void gemm_kernel(int isel, const float* __restrict__ Wg,
                            const float* __restrict__ bvec, int osel,
                            int N, int din, int dout, int post_mode) {
    __shared__ float sW[32 * 152 + 8];
    __shared__ float sX[32 * 36 + 8];
    const float* in = buf(isel);
    float* out = buf(osel);

    const int TM = 4, TN = 4, RT = 8;
    int tid = threadIdx.x;
    int row0 = blockIdx.x * 32;
    int CT = (dout + TN - 1) / TN;
    int ntile = RT * CT;

    float acc[2][TM][TN];
#pragma unroll
    for (int j = 0; j < 2; j++)
#pragma unroll
        for (int m = 0; m < TM; m++)
#pragma unroll
            for (int n = 0; n < TN; n++) acc[j][m][n] = 0.f;

    for (int k0 = 0; k0 < din; k0 += 32) {
        int KT = min(32, din - k0);
        for (int i = tid; i < KT * dout; i += 256) {
            int kk = i / dout, c = i - kk * dout;
            sW[kk * 152 + c] = Wg[(k0 + kk) * dout + c];
        }
        for (int i = tid; i < KT * 32; i += 256) {
            int kk = i >> 5, r = i & 31;
            int row = row0 + r;
            sX[kk * 36 + r] = (row < N) ? in[(long)row * din + k0 + kk] : 0.f;
        }
        __syncthreads();

        for (int j = 0, t = tid; t < ntile; t += 256, j++) {
            int rt = t & (RT - 1), ct = t >> 3;
            int r0 = rt * TM, c0 = ct * TN;
            for (int kk = 0; kk < KT; kk++) {
                float4 av = *(const float4*)&sX[kk * 36 + r0];
                float b[TN];
#pragma unroll
                for (int n = 0; n < TN; n++) b[n] = sW[kk * 152 + c0 + n];
                float a[TM] = {av.x, av.y, av.z, av.w};
#pragma unroll
                for (int m = 0; m < TM; m++)
#pragma unroll
                    for (int n = 0; n < TN; n++)
                        acc[j][m][n] = fmaf(a[m], b[n], acc[j][m][n]);
            }
        }
        __syncthreads();
    }

    for (int j = 0, t = tid; t < ntile; t += 256, j++) {
        int rt = t & (RT - 1), ct = t >> 3;
        int r0 = rt * TM, c0 = ct * TN;
#pragma unroll
        for (int m = 0; m < TM; m++) {
            int row = row0 + r0 + m;
            if (row >= N) continue;
#pragma unroll
            for (int n = 0; n < TN; n++) {
                int c = c0 + n;
                if (c >= dout) continue;
                float v = acc[j][m][n];
                if (post_mode == 0) v = fmaxf(v + bvec[c], 0.f);
                out[(long)row * dout + c] = v;
            }
        }
    }
}

// z = relu(agg + b3) @ Wo + bo ; segment-max via smem-staged encoded atomicMax
__global__ void final_kernel(int hsel, const float* __restrict__ b3,
                             const float* __restrict__ Wo, const float* __restrict__ bo,
                             const int* __restrict__ batch, int N) {
    const float* h = buf(hsel);
    __shared__ unsigned sp[192];
    int tid = threadIdx.x;
    if (tid < 192) sp[tid] = ENC_NEG_INF;
    __syncthreads();
    int i = blockIdx.x * blockDim.x + tid;
    if (i < N) {
        float z0 = bo[0], z1 = bo[1], z2 = bo[2];
        const float* hr = h + (long)i * 50;
#pragma unroll
        for (int c = 0; c < 50; c++) {
            float v = fmaxf(hr[c] + b3[c], 0.f);
            z0 = fmaf(v, Wo[c * 3 + 0], z0);
            z1 = fmaf(v, Wo[c * 3 + 1], z1);
            z2 = fmaf(v, Wo[c * 3 + 2], z2);
        }
        int g = batch[i];
        atomicMax(&sp[g * 3 + 0], enc_f(z0));
        atomicMax(&sp[g * 3 + 1], enc_f(z1));
        atomicMax(&sp[g * 3 + 2], enc_f(z2));
    }
    __syncthreads();
    if (tid < 192 && sp[tid] != ENC_NEG_INF) atomicMax(&g_pool[tid], sp[tid]);
}

__global__ void softmax_kernel(float* __restrict__ out) {
    int g = threadIdx.x;
    if (g < 64) {
        float a = dec_f(g_pool[3 * g + 0]);
        float b = dec_f(g_pool[3 * g + 1]);
        float c = dec_f(g_pool[3 * g + 2]);
        float m = fmaxf(a, fmaxf(b, c));
        float ea = expf(a - m), eb = expf(b - m), ec = expf(c - m);
        float s = ea + eb + ec;
        out[3 * g + 0] = ea / s;
        out[3 * g + 1] = eb / s;
        out[3 * g + 2] = ec / s;
    }
}

extern "C" void kernel_launch(void* const* d_in, const int* in_sizes, int n_in,
                              void* d_out, int out_size) {
    const float* x = (const float*)d_in[0];
    const int* ei = (const int*)d_in[1];
    const int* batch = (const int*)d_in[2];
    const float* W1 = (const float*)d_in[3];
    const float* b1 = (const float*)d_in[4];
    const float* W2 = (const float*)d_in[5];
    const float* b2 = (const float*)d_in[6];
    const float* W3 = (const float*)d_in[7];
    const float* b3 = (const float*)d_in[8];
    const float* Wo = (const float*)d_in[9];
    const float* bo = (const float*)d_in[10];
    float* out = (float*)d_out;

    int N = in_sizes[0] / 36;
    int E = in_sizes[1] / 2;
    const int* src = ei;
    const int* dst = ei + E;
    int nblk = (N + 1023) / 1024;

    const int T = 256;
    int gemm_grid = (N + 31) / 32;
    int gath_grid = (N * 32 + T - 1) / T;  // 1 warp per node

    // CSR build (parallel scan)
    init_kernel<<<(N + T - 1) / T, T>>>(N);
    deg_kernel<<<(E + T - 1) / T, T>>>(dst, E);
    block_sum_kernel<<<nblk, 1024>>>(N);
    scan_part_kernel<<<1, 32>>>(nblk, N);
    rowptr_kernel<<<nblk, 1024>>>(N);
    fill_kernel<<<(E + T - 1) / T, T>>>(src, dst, E);

    // Layer 1: gather(x,36) -> GEMM 36->75 (+b1, relu)
    gather_kernel<<<gath_grid, T>>>(x, -1, 0, N, 36);
    gemm_kernel<<<gemm_grid, T>>>(0, W1, b1, 1, N, 36, 75, 0);

    // Layer 2: gather(75) -> GEMM 75->150 (+b2, relu)
    gather_kernel<<<gath_grid, T>>>(nullptr, 1, 2, N, 75);
    gemm_kernel<<<gemm_grid, T>>>(2, W2, b2, 0, N, 75, 150, 0);

    // Layer 3: GEMM 150->50 (plain) -> gather(50); bias+relu folded into final
    gemm_kernel<<<gemm_grid, T>>>(0, W3, b3, 1, N, 150, 50, 1);
    gather_kernel<<<gath_grid, T>>>(nullptr, 1, 2, N, 50);

    // Fused output layer + pool + softmax
    final_kernel<<<(N + T - 1) / T, T>>>(2, b3, Wo, bo, batch, N);
    softmax_kernel<<<1, 64>>>(out);
}

// round 7
// speedup vs baseline: 1.4204x; 1.0072x over previous
#include <cuda_runtime.h>
#include <math.h>

#define MAXN 50000
#define MAXE 400000

// Scratch buffers (padded row strides: B0 up to 152, B1/B2 up to 76)
__device__ float g_buf0[MAXN * 152];
__device__ float g_buf1[MAXN * 76];
__device__ float g_buf2[MAXN * 76];
__device__ float g_dinv[MAXN];
__device__ int   g_deg[MAXN];
__device__ int   g_cur[MAXN];
__device__ int   g_rowptr[MAXN + 1];
__device__ int   g_col[MAXE];
__device__ int   g_part[64];
__device__ unsigned g_pool[192];

__device__ __forceinline__ float* buf(int i) {
    return i == 0 ? g_buf0 : (i == 1 ? g_buf1 : g_buf2);
}

__device__ __forceinline__ unsigned enc_f(float f) {
    unsigned u = __float_as_uint(f);
    return (u & 0x80000000u) ? ~u : (u | 0x80000000u);
}
__device__ __forceinline__ float dec_f(unsigned e) {
    unsigned u = (e & 0x80000000u) ? (e & 0x7FFFFFFFu) : ~e;
    return __uint_as_float(u);
}
#define ENC_NEG_INF 0x007FFFFFu

__global__ void init_kernel(int N) {
    int i = blockIdx.x * blockDim.x + threadIdx.x;
    if (i < N) { g_deg[i] = 0; g_cur[i] = 0; }
    if (i < 192) g_pool[i] = ENC_NEG_INF;
}

__global__ void deg_kernel(const int* __restrict__ dst, int E) {
    int e = blockIdx.x * blockDim.x + threadIdx.x;
    if (e < E) atomicAdd(&g_deg[dst[e]], 1);
}

// Per-1024-block sum of deg -> g_part[b]; also computes dinv.
__global__ void block_sum_kernel(int N) {
    __shared__ int wsum[32];
    int b = blockIdx.x, tid = threadIdx.x;
    int i = b * 1024 + tid;
    int v = (i < N) ? g_deg[i] : 0;
    if (i < N) g_dinv[i] = rsqrtf((float)(v + 1));  // +1 = self loop
    int s = v;
#pragma unroll
    for (int off = 16; off; off >>= 1) s += __shfl_down_sync(~0u, s, off);
    if ((tid & 31) == 0) wsum[tid >> 5] = s;
    __syncthreads();
    if (tid < 32) {
        int y = wsum[tid];
#pragma unroll
        for (int off = 16; off; off >>= 1) y += __shfl_down_sync(~0u, y, off);
        if (tid == 0) g_part[b] = y;
    }
}

// Single warp: exclusive scan of g_part[0..nblk)
__global__ void scan_part_kernel(int nblk, int N) {
    int lane = threadIdx.x;
    int carry = 0;
    for (int base = 0; base < nblk; base += 32) {
        int i = base + lane;
        int v = (i < nblk) ? g_part[i] : 0;
        int x = v;
#pragma unroll
        for (int off = 1; off < 32; off <<= 1) {
            int t = __shfl_up_sync(~0u, x, off);
            if (lane >= off) x += t;
        }
        if (i < nblk) g_part[i] = carry + x - v;
        carry += __shfl_sync(~0u, x, 31);
    }
    if (lane == 0) g_rowptr[N] = carry;
}

// Per-block exclusive scan of deg + block offset -> rowptr
__global__ void rowptr_kernel(int N) {
    __shared__ int wsum[32];
    int b = blockIdx.x, tid = threadIdx.x, lane = tid & 31, wid = tid >> 5;
    int i = b * 1024 + tid;
    int v = (i < N) ? g_deg[i] : 0;
    int x = v;
#pragma unroll
    for (int off = 1; off < 32; off <<= 1) {
        int t = __shfl_up_sync(~0u, x, off);
        if (lane >= off) x += t;
    }
    if (lane == 31) wsum[wid] = x;
    __syncthreads();
    if (wid == 0) {
        int y = wsum[lane];
#pragma unroll
        for (int off = 1; off < 32; off <<= 1) {
            int t = __shfl_up_sync(~0u, y, off);
            if (lane >= off) y += t;
        }
        wsum[lane] = y;
    }
    __syncthreads();
    int incl = x + (wid ? wsum[wid - 1] : 0);
    if (i < N) g_rowptr[i] = g_part[b] + incl - v;
}

__global__ void fill_kernel(const int* __restrict__ src, const int* __restrict__ dst, int E) {
    int e = blockIdx.x * blockDim.x + threadIdx.x;
    if (e < E) {
        int t = dst[e];
        int pos = atomicAdd(&g_cur[t], 1);
        g_col[g_rowptr[t] + pos] = src[e];
    }
}

// Normalized CSR gather, thread-per-(node, float4 chunk).
// out[t] = dinv[t] * ( dinv[t]*g[t] + sum_{s in N(t)} dinv[s]*g[s] )
// C = row stride in float4 units (stride/4). Input external if gsel<0.
template<int C>
__global__ void gather_kernel(const float* __restrict__ xp, int gsel, int osel, int N) {
    const float* gp = (gsel < 0) ? xp : buf(gsel);
    const float4* __restrict__ G = (const float4*)gp;
    float4* __restrict__ O = (float4*)buf(osel);
    int t = blockIdx.x * blockDim.x + threadIdx.x;
    int w = t / C;
    if (w >= N) return;
    int ch = t - w * C;
    int beg = g_rowptr[w], end = g_rowptr[w + 1];
    float dt = g_dinv[w];
    float4 v = G[w * C + ch];
    float4 acc;
    acc.x = dt * v.x; acc.y = dt * v.y; acc.z = dt * v.z; acc.w = dt * v.w;
    int e = beg;
    for (; e + 2 <= end; e += 2) {
        int c0 = g_col[e], c1 = g_col[e + 1];
        float d0 = g_dinv[c0], d1 = g_dinv[c1];
        float4 v0 = G[c0 * C + ch];
        float4 v1 = G[c1 * C + ch];
        acc.x = fmaf(d0, v0.x, acc.x); acc.y = fmaf(d0, v0.y, acc.y);
        acc.z = fmaf(d0, v0.z, acc.z); acc.w = fmaf(d0, v0.w, acc.w);
        acc.x = fmaf(d1, v1.x, acc.x); acc.y = fmaf(d1, v1.y, acc.y);
        acc.z = fmaf(d1, v1.z, acc.z); acc.w = fmaf(d1, v1.w, acc.w);
    }
    if (e < end) {
        int c0 = g_col[e];
        float d0 = g_dinv[c0];
        float4 v0 = G[c0 * C + ch];
        acc.x = fmaf(d0, v0.x, acc.x); acc.y = fmaf(d0, v0.y, acc.y);
        acc.z = fmaf(d0, v0.z, acc.z); acc.w = fmaf(d0, v0.w, acc.w);
    }
    acc.x *= dt; acc.y *= dt; acc.z *= dt; acc.w *= dt;
    O[w * C + ch] = acc;
}

// f32x2 GEMM: lane = row within 32-row block, warp = 8 output columns.
// Per kk: 1 LDS a (stride-1), 2x ld.shared.v2.b64 b (broadcast), 4x fma.rn.f32x2.
#define KTILE 40
template<int DOUT, int DP2, int STRIN, int STROUT, int RELU>
__global__ void gemm_kernel(int isel, const float* __restrict__ Wg,
                            const float* __restrict__ bvec, int osel,
                            int N, int din) {
    __shared__ float sW[KTILE * DP2];
    __shared__ float sX[KTILE * 33];
    const float* __restrict__ in = buf(isel);
    float* __restrict__ out = buf(osel);
    int tid = threadIdx.x, lane = tid & 31, wid = tid >> 5;
    int row0 = blockIdx.x * 32;
    unsigned swbase = (unsigned)__cvta_generic_to_shared(sW) + wid * 32;  // col c0=wid*8

    unsigned long long acc0 = 0, acc1 = 0, acc2 = 0, acc3 = 0;

    for (int k0 = 0; k0 < din; k0 += KTILE) {
        int KT = min(KTILE, din - k0);
        for (int i = tid; i < KTILE * DP2; i += blockDim.x) {
            int kk = i / DP2, c = i - kk * DP2;
            sW[i] = (kk < KT && c < DOUT) ? Wg[(k0 + kk) * DOUT + c] : 0.f;
        }
        for (int i = tid; i < 32 * KTILE; i += blockDim.x) {
            int r = i / KTILE, kk = i - r * KTILE;
            int row = row0 + r;
            sX[kk * 33 + r] = (row < N && kk < KT) ? in[row * STRIN + k0 + kk] : 0.f;
        }
        __syncthreads();

        unsigned wa = swbase;
#pragma unroll 8
        for (int kk = 0; kk < KT; kk++) {
            float a = sX[kk * 33 + lane];
            unsigned long long ap, b0, b1, b2, b3;
            asm("mov.b64 %0, {%1, %1};" : "=l"(ap) : "r"(__float_as_uint(a)));
            asm("ld.shared.v2.b64 {%0, %1}, [%2];" : "=l"(b0), "=l"(b1) : "r"(wa));
            asm("ld.shared.v2.b64 {%0, %1}, [%2];" : "=l"(b2), "=l"(b3) : "r"(wa + 16));
            asm("fma.rn.f32x2 %0, %1, %2, %0;" : "+l"(acc0) : "l"(ap), "l"(b0));
            asm("fma.rn.f32x2 %0, %1, %2, %0;" : "+l"(acc1) : "l"(ap), "l"(b1));
            asm("fma.rn.f32x2 %0, %1, %2, %0;" : "+l"(acc2) : "l"(ap), "l"(b2));
            asm("fma.rn.f32x2 %0, %1, %2, %0;" : "+l"(acc3) : "l"(ap), "l"(b3));
            wa += DP2 * 4;
        }
        __syncthreads();
    }

    int row = row0 + lane;
    if (row >= N) return;
    float r_[8];
    asm("mov.b64 {%0, %1}, %2;" : "=r"(*(unsigned*)&r_[0]), "=r"(*(unsigned*)&r_[1]) : "l"(acc0));
    asm("mov.b64 {%0, %1}, %2;" : "=r"(*(unsigned*)&r_[2]), "=r"(*(unsigned*)&r_[3]) : "l"(acc1));
    asm("mov.b64 {%0, %1}, %2;" : "=r"(*(unsigned*)&r_[4]), "=r"(*(unsigned*)&r_[5]) : "l"(acc2));
    asm("mov.b64 {%0, %1}, %2;" : "=r"(*(unsigned*)&r_[6]), "=r"(*(unsigned*)&r_[7]) : "l"(acc3));
#pragma unroll
    for (int j = 0; j < 8; j++) {
        int c = wid * 8 + j;
        if (c < STROUT) {
            float vv;
            if (c < DOUT) {
                vv = r_[j];
                if (RELU) vv = fmaxf(vv + bvec[c], 0.f);
            } else {
                vv = 0.f;  // pad column: keep clean zeros for downstream gather
            }
            out[row * STROUT + c] = vv;
        }
    }
}

// z = relu(agg + b3) @ Wo + bo ; segment-max via smem-staged encoded atomicMax
__global__ void final_kernel(int hsel, const float* __restrict__ b3,
                             const float* __restrict__ Wo, const float* __restrict__ bo,
                             const int* __restrict__ batch, int N) {
    const float* h = buf(hsel);
    __shared__ unsigned sp[192];
    int tid = threadIdx.x;
    if (tid < 192) sp[tid] = ENC_NEG_INF;
    __syncthreads();
    int i = blockIdx.x * blockDim.x + tid;
    if (i < N) {
        float z0 = bo[0], z1 = bo[1], z2 = bo[2];
        const float* hr = h + i * 52;
#pragma unroll
        for (int c = 0; c < 50; c++) {
            float v = fmaxf(hr[c] + b3[c], 0.f);
            z0 = fmaf(v, Wo[c * 3 + 0], z0);
            z1 = fmaf(v, Wo[c * 3 + 1], z1);
            z2 = fmaf(v, Wo[c * 3 + 2], z2);
        }
        int g = batch[i];
        atomicMax(&sp[g * 3 + 0], enc_f(z0));
        atomicMax(&sp[g * 3 + 1], enc_f(z1));
        atomicMax(&sp[g * 3 + 2], enc_f(z2));
    }
    __syncthreads();
    if (tid < 192 && sp[tid] != ENC_NEG_INF) atomicMax(&g_pool[tid], sp[tid]);
}

__global__ void softmax_kernel(float* __restrict__ out) {
    int g = threadIdx.x;
    if (g < 64) {
        float a = dec_f(g_pool[3 * g + 0]);
        float b = dec_f(g_pool[3 * g + 1]);
        float c = dec_f(g_pool[3 * g + 2]);
        float m = fmaxf(a, fmaxf(b, c));
        float ea = expf(a - m), eb = expf(b - m), ec = expf(c - m);
        float s = ea + eb + ec;
        out[3 * g + 0] = ea / s;
        out[3 * g + 1] = eb / s;
        out[3 * g + 2] = ec / s;
    }
}

extern "C" void kernel_launch(void* const* d_in, const int* in_sizes, int n_in,
                              void* d_out, int out_size) {
    const float* x = (const float*)d_in[0];
    const int* ei = (const int*)d_in[1];
    const int* batch = (const int*)d_in[2];
    const float* W1 = (const float*)d_in[3];
    const float* b1 = (const float*)d_in[4];
    const float* W2 = (const float*)d_in[5];
    const float* b2 = (const float*)d_in[6];
    const float* W3 = (const float*)d_in[7];
    const float* b3 = (const float*)d_in[8];
    const float* Wo = (const float*)d_in[9];
    const float* bo = (const float*)d_in[10];
    float* out = (float*)d_out;

    int N = in_sizes[0] / 36;
    int E = in_sizes[1] / 2;
    const int* src = ei;
    const int* dst = ei + E;
    int nblk = (N + 1023) / 1024;

    const int T = 256;
    int gemm_grid = (N + 31) / 32;

    // CSR build (parallel scan)
    init_kernel<<<(N + T - 1) / T, T>>>(N);
    deg_kernel<<<(E + T - 1) / T, T>>>(dst, E);
    block_sum_kernel<<<nblk, 1024>>>(N);
    scan_part_kernel<<<1, 32>>>(nblk, N);
    rowptr_kernel<<<nblk, 1024>>>(N);
    fill_kernel<<<(E + T - 1) / T, T>>>(src, dst, E);

    // Layer 1: gather(x, str36, C=9) -> B0 ; GEMM 36->75 (relu+b1) -> B1 (str76)
    gather_kernel<9><<<(N * 9 + T - 1) / T, T>>>(x, -1, 0, N);
    gemm_kernel<75, 80, 36, 76, 1><<<gemm_grid, 320>>>(0, W1, b1, 1, N, 36);

    // Layer 2: gather(B1, str76, C=19) -> B2 ; GEMM 75->150 (relu+b2) -> B0 (str152)
    gather_kernel<19><<<(N * 19 + T - 1) / T, T>>>(nullptr, 1, 2, N);
    gemm_kernel<150, 152, 76, 152, 1><<<gemm_grid, 608>>>(2, W2, b2, 0, N, 75);

    // Layer 3: GEMM 150->50 (plain) -> B1 (str52) ; gather(B1, str52, C=13) -> B2
    gemm_kernel<50, 56, 152, 52, 0><<<gemm_grid, 224>>>(0, W3, b3, 1, N, 150);
    gather_kernel<13><<<(N * 13 + T - 1) / T, T>>>(nullptr, 1, 2, N);

    // Fused output layer + pool + softmax (bias b3 + relu folded here)
    final_kernel<<<(N + T - 1) / T, T>>>(2, b3, Wo, bo, batch, N);
    softmax_kernel<<<1, 64>>>(out);
}